// round 8
// baseline (speedup 1.0000x reference)
#include <cuda_runtime.h>
#include <math.h>
#include <stdint.h>

#define LSEQ 128
#define BATCH 1024
#define HDIM 256
#define DDIM 512
#define EXTC 33
#define OUTC 16
#define ODEH 128

typedef unsigned long long ull;

// ---------------- scratch (device globals; no allocation allowed) ------------
__device__ __align__(16) float g_X[(size_t)LSEQ * BATCH * DDIM];   // embeddings [L,B,512]
__device__ __align__(16) float g_hn[(size_t)BATCH * DDIM];         // state entering current step
__device__ __align__(16) float g_hnmid[(size_t)BATCH * DDIM];      // post-GRU pre-ODE

// ---------------- packed f32x2 helpers ---------------------------------------
__device__ __forceinline__ ull pack2(float x, float y) {
    ull r;
    asm("mov.b64 %0, {%1,%2};" : "=l"(r) : "f"(x), "f"(y));
    return r;
}
__device__ __forceinline__ float2 unpack2(ull v) {
    float2 r;
    asm("mov.b64 {%0,%1}, %2;" : "=f"(r.x), "=f"(r.y) : "l"(v));
    return r;
}
__device__ __forceinline__ void fma2(ull& d, ull a, ull b) {
    asm("fma.rn.f32x2 %0, %1, %2, %0;" : "+l"(d) : "l"(a), "l"(b));
}

// ---------------- init: h0 = 0, y[0] = bLy -----------------------------------
__global__ void init_kernel(float* __restrict__ out, const float* __restrict__ bLy) {
    int i = blockIdx.x * blockDim.x + threadIdx.x;
    if (i < BATCH * DDIM) g_hn[i] = 0.f;
    if (i < BATCH * OUTC) out[i] = bLy[i & 15];
}

// ---------------- embeddings: X = [tanh(u@Wu+bu) | tanh(obs@Wx+bx)] ----------
__global__ void __launch_bounds__(256) embed_kernel(
    const float* __restrict__ ext, const float* __restrict__ obs,
    const float* __restrict__ Wu, const float* __restrict__ bu,
    const float* __restrict__ Wx, const float* __restrict__ bx)
{
    __shared__ float es[16][32];
    __shared__ float os[16][16];
    const int tid = threadIdx.x;
    const size_t base = (size_t)blockIdx.x * 16;   // row into L*B

#pragma unroll
    for (int i = 0; i < 2; i++) {
        int idx = tid + i * 256;
        int r = idx >> 5, c = idx & 31;
        es[r][c] = ext[(base + r) * EXTC + c];
    }
    { int r = tid >> 4, c = tid & 15; os[r][c] = obs[(base + r) * OUTC + c]; }
    __syncthreads();

    const int c = tid;  // 0..255 output column
    float acc[16];
#pragma unroll
    for (int r = 0; r < 16; r++) acc[r] = bu[c];
    for (int i = 0; i < 32; i++) {
        float w = Wu[i * 256 + c];
#pragma unroll
        for (int r = 0; r < 16; r++) acc[r] += es[r][i] * w;
    }
#pragma unroll
    for (int r = 0; r < 16; r++) g_X[(base + r) * DDIM + c] = tanhf(acc[r]);

#pragma unroll
    for (int r = 0; r < 16; r++) acc[r] = bx[c];
    for (int i = 0; i < 16; i++) {
        float w = Wx[i * 256 + c];
#pragma unroll
        for (int r = 0; r < 16; r++) acc[r] += os[r][i] * w;
    }
#pragma unroll
    for (int r = 0; r < 16; r++) g_X[(base + r) * DDIM + 256 + c] = tanhf(acc[r]);
}

// ---------------- per-step GRU GEMM + gates ----------------------------------
// Tile: M=64 rows x (3 gates x 64 cols), K=1024 (512 from X_t, 512 from h).
// 256 threads = 16(ty) x 16(tx); thread tile = 4 rows x 4 cols (2 f32x2 pairs) x gates.
// 4 accumulator sets: r (K=1024), z (K=1024), gi_n (K=512 X-phase), gh_n (K=512 h-phase).

struct Frag { float4 a, b0, b1, b2; };

__device__ __forceinline__ Frag fetch_tile(
    const float* __restrict__ Xt, const float* __restrict__ Wih,
    const float* __restrict__ Whh, int b0, int j0, int kt, int tid)
{
    Frag f;
    const int m = tid >> 2, q = tid & 3;
    const float* asrc;
    const float* W;
    int kc;
    if (kt < 512) { asrc = Xt;   W = Wih; kc = kt; }
    else          { asrc = g_hn; W = Whh; kc = kt - 512; }
    f.a  = *(const float4*)&asrc[(size_t)(b0 + m) * DDIM + kc + q * 4];
    f.b0 = *(const float4*)&W[(size_t)(0 * 512 + j0 + m) * DDIM + kc + q * 4];
    f.b1 = *(const float4*)&W[(size_t)(1 * 512 + j0 + m) * DDIM + kc + q * 4];
    f.b2 = *(const float4*)&W[(size_t)(2 * 512 + j0 + m) * DDIM + kc + q * 4];
    return f;
}

__device__ __forceinline__ void commit_tile(
    const Frag& f, float (*As)[64], float (*Bs)[16][64], int tid)
{
    const int m = tid >> 2, q = tid & 3;
    As[q * 4 + 0][m] = f.a.x;  As[q * 4 + 1][m] = f.a.y;
    As[q * 4 + 2][m] = f.a.z;  As[q * 4 + 3][m] = f.a.w;
    Bs[0][q * 4 + 0][m] = f.b0.x; Bs[0][q * 4 + 1][m] = f.b0.y;
    Bs[0][q * 4 + 2][m] = f.b0.z; Bs[0][q * 4 + 3][m] = f.b0.w;
    Bs[1][q * 4 + 0][m] = f.b1.x; Bs[1][q * 4 + 1][m] = f.b1.y;
    Bs[1][q * 4 + 2][m] = f.b1.z; Bs[1][q * 4 + 3][m] = f.b1.w;
    Bs[2][q * 4 + 0][m] = f.b2.x; Bs[2][q * 4 + 1][m] = f.b2.y;
    Bs[2][q * 4 + 2][m] = f.b2.z; Bs[2][q * 4 + 3][m] = f.b2.w;
}

__device__ __forceinline__ void mac16(
    const float (*As)[64], const float (*Bs)[16][64], int ty, int tx,
    ull (&ar)[4][2], ull (&az)[4][2], ull (&an)[4][2])
{
#pragma unroll
    for (int kk = 0; kk < 16; kk++) {
        float4 av = *(const float4*)&As[kk][ty * 4];
        ull a0 = pack2(av.x, av.x), a1 = pack2(av.y, av.y);
        ull a2 = pack2(av.z, av.z), a3 = pack2(av.w, av.w);
        ulonglong2 br = *(const ulonglong2*)&Bs[0][kk][tx * 4];
        ulonglong2 bz = *(const ulonglong2*)&Bs[1][kk][tx * 4];
        ulonglong2 bn = *(const ulonglong2*)&Bs[2][kk][tx * 4];
        fma2(ar[0][0], a0, br.x); fma2(ar[0][1], a0, br.y);
        fma2(az[0][0], a0, bz.x); fma2(az[0][1], a0, bz.y);
        fma2(an[0][0], a0, bn.x); fma2(an[0][1], a0, bn.y);
        fma2(ar[1][0], a1, br.x); fma2(ar[1][1], a1, br.y);
        fma2(az[1][0], a1, bz.x); fma2(az[1][1], a1, bz.y);
        fma2(an[1][0], a1, bn.x); fma2(an[1][1], a1, bn.y);
        fma2(ar[2][0], a2, br.x); fma2(ar[2][1], a2, br.y);
        fma2(az[2][0], a2, bz.x); fma2(az[2][1], a2, bz.y);
        fma2(an[2][0], a2, bn.x); fma2(an[2][1], a2, bn.y);
        fma2(ar[3][0], a3, br.x); fma2(ar[3][1], a3, br.y);
        fma2(az[3][0], a3, bz.x); fma2(az[3][1], a3, bz.y);
        fma2(an[3][0], a3, bn.x); fma2(an[3][1], a3, bn.y);
    }
}

__global__ void __launch_bounds__(256) gru_step(
    int t,
    const float* __restrict__ Wih, const float* __restrict__ Whh,
    const float* __restrict__ bih, const float* __restrict__ bhh)
{
    __shared__ __align__(16) float As[2][16][64];
    __shared__ __align__(16) float Bs[2][3][16][64];

    const float* Xt = g_X + (size_t)t * BATCH * DDIM;
    const int tid = threadIdx.x;
    const int tx = tid & 15, ty = tid >> 4;
    const int b0 = blockIdx.x * 64, j0 = blockIdx.y * 64;

    ull accr[4][2], accz[4][2], accn1[4][2], accn2[4][2];
    const ull z2 = pack2(0.f, 0.f);
#pragma unroll
    for (int i = 0; i < 4; i++)
#pragma unroll
        for (int p = 0; p < 2; p++) {
            accr[i][p] = z2; accz[i][p] = z2; accn1[i][p] = z2; accn2[i][p] = z2;
        }

    Frag f0 = fetch_tile(Xt, Wih, Whh, b0, j0, 0, tid);
    commit_tile(f0, As[0], Bs[0], tid);
    __syncthreads();

    int cur = 0;
    for (int tile = 0; tile < 64; ++tile) {
        Frag nf;
        if (tile < 63) nf = fetch_tile(Xt, Wih, Whh, b0, j0, (tile + 1) * 16, tid);
        if (tile < 32) mac16(As[cur], Bs[cur], ty, tx, accr, accz, accn1);
        else           mac16(As[cur], Bs[cur], ty, tx, accr, accz, accn2);
        if (tile < 63) commit_tile(nf, As[cur ^ 1], Bs[cur ^ 1], tid);
        __syncthreads();
        cur ^= 1;
    }

    // epilogue: gates + state blend
#pragma unroll
    for (int p = 0; p < 2; p++) {
#pragma unroll
        for (int e = 0; e < 2; e++) {
            const int jj = j0 + tx * 4 + p * 2 + e;
            const float bir = __ldg(&bih[jj]),        bhr = __ldg(&bhh[jj]);
            const float biz = __ldg(&bih[512 + jj]),  bhz = __ldg(&bhh[512 + jj]);
            const float bin = __ldg(&bih[1024 + jj]), bhn = __ldg(&bhh[1024 + jj]);
#pragma unroll
            for (int i = 0; i < 4; i++) {
                const int b = b0 + ty * 4 + i;
                float2 rv2 = unpack2(accr[i][p]);
                float2 zv2 = unpack2(accz[i][p]);
                float2 n1v2 = unpack2(accn1[i][p]);
                float2 n2v2 = unpack2(accn2[i][p]);
                float rv = e ? rv2.y : rv2.x;
                float zv = e ? zv2.y : zv2.x;
                float n1v = e ? n1v2.y : n1v2.x;
                float n2v = e ? n2v2.y : n2v2.x;
                float r = 1.f / (1.f + expf(-(rv + bir + bhr)));
                float z = 1.f / (1.f + expf(-(zv + biz + bhz)));
                float n = tanhf(n1v + bin + r * (n2v + bhn));
                float hp = g_hn[(size_t)b * DDIM + jj];
                g_hnmid[(size_t)b * DDIM + jj] = (1.f - z) * n + z * hp;
            }
        }
    }
}

// ---------------- per-step ODE MLP + state update + output projection --------
// 128 blocks x 256 threads; each block owns 8 consecutive batch rows.
__global__ void __launch_bounds__(256) ode_step(
    int t, const float* __restrict__ ext,
    const float* __restrict__ W1, const float* __restrict__ b1,
    const float* __restrict__ W2, const float* __restrict__ b2,
    const float* __restrict__ WLy, const float* __restrict__ bLy,
    float* __restrict__ out)
{
    __shared__ __align__(16) float hs[8][512];
    __shared__ float z1s[8][128];
    __shared__ float dts[8];
    __shared__ float red[2][8][16];

    const int tid = threadIdx.x;
    const int b0 = blockIdx.x * 8;

    // load 8 full state rows (contiguous 16 KB) vectorized
    {
        const float4* src = (const float4*)(g_hnmid + (size_t)b0 * DDIM);
        float4* dst = (float4*)&hs[0][0];
#pragma unroll
        for (int i = 0; i < 4; i++) dst[tid + i * 256] = src[tid + i * 256];
    }
    if (tid < 8)
        dts[tid] = ext[((size_t)t * BATCH + b0 + tid) * EXTC + 32];
    __syncthreads();

    // z1 = tanh(h @ W1 + b1)   (h = first 256 of state)
    {
        const int m = tid & 127;
        const int rg = tid >> 7;  // 0/1 -> rows rg*4..rg*4+3
        float acc[4];
#pragma unroll
        for (int i = 0; i < 4; i++) acc[i] = b1[m];
#pragma unroll 8
        for (int k = 0; k < 256; k++) {
            float w = W1[k * 128 + m];
#pragma unroll
            for (int i = 0; i < 4; i++) acc[i] += hs[rg * 4 + i][k] * w;
        }
#pragma unroll
        for (int i = 0; i < 4; i++) z1s[rg * 4 + i][m] = tanhf(acc[i]);
    }
    __syncthreads();

    // f = z1 @ W2 + b2; h_out = h + dt*f; write new state; keep h_out in smem for y
    {
        const int d = tid;  // 0..255
        float facc[8];
#pragma unroll
        for (int r = 0; r < 8; r++) facc[r] = b2[d];
#pragma unroll 8
        for (int m2 = 0; m2 < 128; m2++) {
            float w = W2[m2 * 256 + d];
#pragma unroll
            for (int r = 0; r < 8; r++) facc[r] += z1s[r][m2] * w;
        }
#pragma unroll
        for (int r = 0; r < 8; r++) {
            float hout = hs[r][d] + dts[r] * facc[r];
            g_hn[(size_t)(b0 + r) * DDIM + d] = hout;
            g_hn[(size_t)(b0 + r) * DDIM + 256 + d] = hs[r][256 + d];  // c passthrough
            hs[r][d] = hout;
        }
    }
    __syncthreads();

    // y[t+1] = hn_out @ WLy + bLy  (y[0] handled by init; step L-1 writes nothing)
    if (t + 1 < LSEQ) {
        const int o = tid & 15;
        const int r = (tid >> 4) & 7;
        const int half = tid >> 7;
        const int dbase = half * 256;
        float p0 = 0.f, p1 = 0.f, p2 = 0.f, p3 = 0.f;
#pragma unroll 4
        for (int dd = 0; dd < 256; dd += 4) {
            p0 += hs[r][dbase + dd + 0] * WLy[(dbase + dd + 0) * 16 + o];
            p1 += hs[r][dbase + dd + 1] * WLy[(dbase + dd + 1) * 16 + o];
            p2 += hs[r][dbase + dd + 2] * WLy[(dbase + dd + 2) * 16 + o];
            p3 += hs[r][dbase + dd + 3] * WLy[(dbase + dd + 3) * 16 + o];
        }
        red[half][r][o] = (p0 + p1) + (p2 + p3);
        __syncthreads();
        if (tid < 128) {
            int o2 = tid & 15, r2 = tid >> 4;
            out[((size_t)(t + 1) * BATCH + b0 + r2) * 16 + o2] =
                red[0][r2][o2] + red[1][r2][o2] + bLy[o2];
        }
    }
}

// ---------------- launch ------------------------------------------------------
extern "C" void kernel_launch(void* const* d_in, const int* in_sizes, int n_in,
                              void* d_out, int out_size)
{
    (void)in_sizes; (void)n_in; (void)out_size;
    const float* ext = (const float*)d_in[0];
    const float* obs = (const float*)d_in[1];
    const float* Wu  = (const float*)d_in[2];
    const float* bu  = (const float*)d_in[3];
    const float* Wx  = (const float*)d_in[4];
    const float* bx  = (const float*)d_in[5];
    const float* Wih = (const float*)d_in[6];
    const float* Whh = (const float*)d_in[7];
    const float* bih = (const float*)d_in[8];
    const float* bhh = (const float*)d_in[9];
    const float* W1  = (const float*)d_in[10];
    const float* b1  = (const float*)d_in[11];
    const float* W2  = (const float*)d_in[12];
    const float* b2  = (const float*)d_in[13];
    const float* WLy = (const float*)d_in[14];
    const float* bLy = (const float*)d_in[15];
    float* out = (float*)d_out;

    init_kernel<<<2048, 256>>>(out, bLy);
    embed_kernel<<<(LSEQ * BATCH) / 16, 256>>>(ext, obs, Wu, bu, Wx, bx);
    for (int t = 0; t < LSEQ; t++) {
        gru_step<<<dim3(16, 8), 256>>>(t, Wih, Whh, bih, bhh);
        ode_step<<<128, 256>>>(t, ext, W1, b1, W2, b2, WLy, bLy, out);
    }
}

// round 9
// speedup vs baseline: 1.1371x; 1.1371x over previous
#include <cuda_runtime.h>
#include <math.h>
#include <stdint.h>

#define LSEQ 128
#define BATCH 1024
#define HDIM 256
#define DDIM 512
#define EXTC 33
#define OUTC 16
#define ODEH 128

typedef unsigned long long ull;

// ---------------- scratch (device globals; no allocation allowed) ------------
__device__ __align__(16) float g_X[(size_t)LSEQ * BATCH * DDIM];   // embeddings [L,B,512]
__device__ __align__(16) float g_hn[(size_t)BATCH * DDIM];         // state entering current step
__device__ __align__(16) float g_hnmid[(size_t)BATCH * DDIM];      // post-GRU pre-ODE

// ---------------- packed f32x2 helpers ---------------------------------------
__device__ __forceinline__ ull pack2(float x, float y) {
    ull r;
    asm("mov.b64 %0, {%1,%2};" : "=l"(r) : "f"(x), "f"(y));
    return r;
}
__device__ __forceinline__ float2 unpack2(ull v) {
    float2 r;
    asm("mov.b64 {%0,%1}, %2;" : "=f"(r.x), "=f"(r.y) : "l"(v));
    return r;
}
__device__ __forceinline__ void fma2(ull& d, ull a, ull b) {
    asm("fma.rn.f32x2 %0, %1, %2, %0;" : "+l"(d) : "l"(a), "l"(b));
}

// ---------------- init: h0 = 0, y[0] = bLy -----------------------------------
__global__ void init_kernel(float* __restrict__ out, const float* __restrict__ bLy) {
    int i = blockIdx.x * blockDim.x + threadIdx.x;
    if (i < BATCH * DDIM) g_hn[i] = 0.f;
    if (i < BATCH * OUTC) out[i] = bLy[i & 15];
}

// ---------------- embeddings: X = [tanh(u@Wu+bu) | tanh(obs@Wx+bx)] ----------
__global__ void __launch_bounds__(256) embed_kernel(
    const float* __restrict__ ext, const float* __restrict__ obs,
    const float* __restrict__ Wu, const float* __restrict__ bu,
    const float* __restrict__ Wx, const float* __restrict__ bx)
{
    __shared__ float es[16][32];
    __shared__ float os[16][16];
    const int tid = threadIdx.x;
    const size_t base = (size_t)blockIdx.x * 16;   // row into L*B

#pragma unroll
    for (int i = 0; i < 2; i++) {
        int idx = tid + i * 256;
        int r = idx >> 5, c = idx & 31;
        es[r][c] = ext[(base + r) * EXTC + c];
    }
    { int r = tid >> 4, c = tid & 15; os[r][c] = obs[(base + r) * OUTC + c]; }
    __syncthreads();

    const int c = tid;  // 0..255 output column
    float acc[16];
#pragma unroll
    for (int r = 0; r < 16; r++) acc[r] = bu[c];
    for (int i = 0; i < 32; i++) {
        float w = Wu[i * 256 + c];
#pragma unroll
        for (int r = 0; r < 16; r++) acc[r] += es[r][i] * w;
    }
#pragma unroll
    for (int r = 0; r < 16; r++) g_X[(base + r) * DDIM + c] = tanhf(acc[r]);

#pragma unroll
    for (int r = 0; r < 16; r++) acc[r] = bx[c];
    for (int i = 0; i < 16; i++) {
        float w = Wx[i * 256 + c];
#pragma unroll
        for (int r = 0; r < 16; r++) acc[r] += os[r][i] * w;
    }
#pragma unroll
    for (int r = 0; r < 16; r++) g_X[(base + r) * DDIM + 256 + c] = tanhf(acc[r]);
}

// ---------------- per-step GRU GEMM + gates ----------------------------------
// Tile: M=64 rows x (3 gates x 64 cols), K=1024 (512 from X_t, 512 from h).
// 256 threads = 16(ty) x 16(tx); thread tile = 4 rows x 4 cols (2 f32x2 pairs) x gates.
// 4 accumulator sets: r (K=1024), z (K=1024), gi_n (K=512 X-phase), gh_n (K=512 h-phase).

struct Frag { float4 a, b0, b1, b2; };

__device__ __forceinline__ Frag fetch_tile(
    const float* __restrict__ Xt, const float* __restrict__ Wih,
    const float* __restrict__ Whh, int b0, int j0, int kt, int tid)
{
    Frag f;
    const int m = tid >> 2, q = tid & 3;
    const float* asrc;
    const float* W;
    int kc;
    if (kt < 512) { asrc = Xt;   W = Wih; kc = kt; }
    else          { asrc = g_hn; W = Whh; kc = kt - 512; }
    f.a  = *(const float4*)&asrc[(size_t)(b0 + m) * DDIM + kc + q * 4];
    f.b0 = *(const float4*)&W[(size_t)(0 * 512 + j0 + m) * DDIM + kc + q * 4];
    f.b1 = *(const float4*)&W[(size_t)(1 * 512 + j0 + m) * DDIM + kc + q * 4];
    f.b2 = *(const float4*)&W[(size_t)(2 * 512 + j0 + m) * DDIM + kc + q * 4];
    return f;
}

__device__ __forceinline__ void commit_tile(
    const Frag& f, float (*As)[64], float (*Bs)[16][64], int tid)
{
    const int m = tid >> 2, q = tid & 3;
    As[q * 4 + 0][m] = f.a.x;  As[q * 4 + 1][m] = f.a.y;
    As[q * 4 + 2][m] = f.a.z;  As[q * 4 + 3][m] = f.a.w;
    Bs[0][q * 4 + 0][m] = f.b0.x; Bs[0][q * 4 + 1][m] = f.b0.y;
    Bs[0][q * 4 + 2][m] = f.b0.z; Bs[0][q * 4 + 3][m] = f.b0.w;
    Bs[1][q * 4 + 0][m] = f.b1.x; Bs[1][q * 4 + 1][m] = f.b1.y;
    Bs[1][q * 4 + 2][m] = f.b1.z; Bs[1][q * 4 + 3][m] = f.b1.w;
    Bs[2][q * 4 + 0][m] = f.b2.x; Bs[2][q * 4 + 1][m] = f.b2.y;
    Bs[2][q * 4 + 2][m] = f.b2.z; Bs[2][q * 4 + 3][m] = f.b2.w;
}

__device__ __forceinline__ void mac16(
    const float (*As)[64], const float (*Bs)[16][64], int ty, int tx,
    ull (&ar)[4][2], ull (&az)[4][2], ull (&an)[4][2])
{
#pragma unroll
    for (int kk = 0; kk < 16; kk++) {
        float4 av = *(const float4*)&As[kk][ty * 4];
        ull a0 = pack2(av.x, av.x), a1 = pack2(av.y, av.y);
        ull a2 = pack2(av.z, av.z), a3 = pack2(av.w, av.w);
        ulonglong2 br = *(const ulonglong2*)&Bs[0][kk][tx * 4];
        ulonglong2 bz = *(const ulonglong2*)&Bs[1][kk][tx * 4];
        ulonglong2 bn = *(const ulonglong2*)&Bs[2][kk][tx * 4];
        fma2(ar[0][0], a0, br.x); fma2(ar[0][1], a0, br.y);
        fma2(az[0][0], a0, bz.x); fma2(az[0][1], a0, bz.y);
        fma2(an[0][0], a0, bn.x); fma2(an[0][1], a0, bn.y);
        fma2(ar[1][0], a1, br.x); fma2(ar[1][1], a1, br.y);
        fma2(az[1][0], a1, bz.x); fma2(az[1][1], a1, bz.y);
        fma2(an[1][0], a1, bn.x); fma2(an[1][1], a1, bn.y);
        fma2(ar[2][0], a2, br.x); fma2(ar[2][1], a2, br.y);
        fma2(az[2][0], a2, bz.x); fma2(az[2][1], a2, bz.y);
        fma2(an[2][0], a2, bn.x); fma2(an[2][1], a2, bn.y);
        fma2(ar[3][0], a3, br.x); fma2(ar[3][1], a3, br.y);
        fma2(az[3][0], a3, bz.x); fma2(az[3][1], a3, bz.y);
        fma2(an[3][0], a3, bn.x); fma2(an[3][1], a3, bn.y);
    }
}

__global__ void __launch_bounds__(256) gru_step(
    int t,
    const float* __restrict__ Wih, const float* __restrict__ Whh,
    const float* __restrict__ bih, const float* __restrict__ bhh)
{
    __shared__ __align__(16) float As[2][16][64];
    __shared__ __align__(16) float Bs[2][3][16][64];

    const float* Xt = g_X + (size_t)t * BATCH * DDIM;
    const int tid = threadIdx.x;
    const int tx = tid & 15, ty = tid >> 4;
    const int b0 = blockIdx.x * 64, j0 = blockIdx.y * 64;

    ull accr[4][2], accz[4][2], accn1[4][2], accn2[4][2];
    const ull z2 = pack2(0.f, 0.f);
#pragma unroll
    for (int i = 0; i < 4; i++)
#pragma unroll
        for (int p = 0; p < 2; p++) {
            accr[i][p] = z2; accz[i][p] = z2; accn1[i][p] = z2; accn2[i][p] = z2;
        }

    Frag f0 = fetch_tile(Xt, Wih, Whh, b0, j0, 0, tid);
    commit_tile(f0, As[0], Bs[0], tid);
    __syncthreads();

    int cur = 0;
    for (int tile = 0; tile < 64; ++tile) {
        Frag nf;
        if (tile < 63) nf = fetch_tile(Xt, Wih, Whh, b0, j0, (tile + 1) * 16, tid);
        if (tile < 32) mac16(As[cur], Bs[cur], ty, tx, accr, accz, accn1);
        else           mac16(As[cur], Bs[cur], ty, tx, accr, accz, accn2);
        if (tile < 63) commit_tile(nf, As[cur ^ 1], Bs[cur ^ 1], tid);
        __syncthreads();
        cur ^= 1;
    }

    // epilogue: gates + state blend
#pragma unroll
    for (int p = 0; p < 2; p++) {
#pragma unroll
        for (int e = 0; e < 2; e++) {
            const int jj = j0 + tx * 4 + p * 2 + e;
            const float bir = __ldg(&bih[jj]),        bhr = __ldg(&bhh[jj]);
            const float biz = __ldg(&bih[512 + jj]),  bhz = __ldg(&bhh[512 + jj]);
            const float bin = __ldg(&bih[1024 + jj]), bhn = __ldg(&bhh[1024 + jj]);
#pragma unroll
            for (int i = 0; i < 4; i++) {
                const int b = b0 + ty * 4 + i;
                float2 rv2 = unpack2(accr[i][p]);
                float2 zv2 = unpack2(accz[i][p]);
                float2 n1v2 = unpack2(accn1[i][p]);
                float2 n2v2 = unpack2(accn2[i][p]);
                float rv = e ? rv2.y : rv2.x;
                float zv = e ? zv2.y : zv2.x;
                float n1v = e ? n1v2.y : n1v2.x;
                float n2v = e ? n2v2.y : n2v2.x;
                float r = 1.f / (1.f + expf(-(rv + bir + bhr)));
                float z = 1.f / (1.f + expf(-(zv + biz + bhz)));
                float n = tanhf(n1v + bin + r * (n2v + bhn));
                float hp = g_hn[(size_t)b * DDIM + jj];
                g_hnmid[(size_t)b * DDIM + jj] = (1.f - z) * n + z * hp;
            }
        }
    }
}

// ---------------- per-step ODE MLP + state update + output projection --------
// v2: 128 blocks x 512 threads; 8 batch rows per block; split-K in every phase
// so all 512 threads are busy with 8 accumulators and short (64-iter) k-loops.
// Partials reduced through a reused 16KB smem buffer.
__global__ void __launch_bounds__(512) ode_step(
    int t, const float* __restrict__ ext,
    const float* __restrict__ W1, const float* __restrict__ b1,
    const float* __restrict__ W2, const float* __restrict__ b2,
    const float* __restrict__ WLy, const float* __restrict__ bLy,
    float* __restrict__ out)
{
    __shared__ __align__(16) float hs[8][512];     // 16KB state rows
    __shared__ float z1s[8][128];                  // 4KB
    __shared__ __align__(16) float part[4096];     // 16KB (z1 partials, then f partials)
    __shared__ float yred[4][8][16];               // 2KB
    __shared__ float dts[8];

    const int tid = threadIdx.x;
    const int b0 = blockIdx.x * 8;

    // load 8 full state rows (contiguous 16 KB), 1024 float4 / 512 threads
    {
        const float4* src = (const float4*)(g_hnmid + (size_t)b0 * DDIM);
        float4* dst = (float4*)&hs[0][0];
        dst[tid]       = src[tid];
        dst[tid + 512] = src[tid + 512];
    }
    if (tid < 8)
        dts[tid] = ext[((size_t)t * BATCH + b0 + tid) * EXTC + 32];
    __syncthreads();

    // ---- phase 1: z1 partials.  512 thr = 128 m-cols x 4 k-groups(64) ------
    {
        const int m = tid & 127;
        const int g = tid >> 7;            // 0..3
        const int kb = g * 64;
        float acc[8];
#pragma unroll
        for (int r = 0; r < 8; r++) acc[r] = 0.f;
#pragma unroll 8
        for (int k = 0; k < 64; k++) {
            float w = W1[(kb + k) * 128 + m];
#pragma unroll
            for (int r = 0; r < 8; r++) acc[r] += hs[r][kb + k] * w;
        }
#pragma unroll
        for (int r = 0; r < 8; r++) part[(g * 8 + r) * 128 + m] = acc[r];
    }
    __syncthreads();
    // reduce z1: 1024 outputs / 512 threads
    {
#pragma unroll
        for (int i = 0; i < 2; i++) {
            int idx = tid + i * 512;
            int r = idx >> 7, m = idx & 127;
            float v = b1[m] + (part[(0 * 8 + r) * 128 + m] + part[(1 * 8 + r) * 128 + m])
                            + (part[(2 * 8 + r) * 128 + m] + part[(3 * 8 + r) * 128 + m]);
            z1s[r][m] = tanhf(v);
        }
    }
    __syncthreads();

    // ---- phase 2: f partials.  512 thr = 256 d-cols x 2 k-groups(64) -------
    {
        const int d = tid & 255;
        const int g = tid >> 8;            // 0..1
        const int kb = g * 64;
        float acc[8];
#pragma unroll
        for (int r = 0; r < 8; r++) acc[r] = 0.f;
#pragma unroll 8
        for (int k = 0; k < 64; k++) {
            float w = W2[(kb + k) * 256 + d];
#pragma unroll
            for (int r = 0; r < 8; r++) acc[r] += z1s[r][kb + k] * w;
        }
#pragma unroll
        for (int r = 0; r < 8; r++) part[(g * 8 + r) * 256 + d] = acc[r];
    }
    __syncthreads();
    // reduce f + state update: 2048 outputs / 512 threads
    {
#pragma unroll
        for (int i = 0; i < 4; i++) {
            int idx = tid + i * 512;
            int r = idx >> 8, d = idx & 255;
            float f = b2[d] + part[(0 * 8 + r) * 256 + d] + part[(1 * 8 + r) * 256 + d];
            float hout = hs[r][d] + dts[r] * f;
            g_hn[(size_t)(b0 + r) * DDIM + d]       = hout;
            g_hn[(size_t)(b0 + r) * DDIM + 256 + d] = hs[r][256 + d];  // c passthrough
            hs[r][d] = hout;
        }
    }
    __syncthreads();

    // ---- phase 3: y[t+1] = hn_out @ WLy + bLy ------------------------------
    // 512 thr = 16 o x 8 r x 4 d-groups(128)
    if (t + 1 < LSEQ) {
        const int o = tid & 15;
        const int r = (tid >> 4) & 7;
        const int q = tid >> 7;            // 0..3
        const int dbase = q * 128;
        float p0 = 0.f, p1 = 0.f, p2 = 0.f, p3 = 0.f;
#pragma unroll 8
        for (int dd = 0; dd < 128; dd += 4) {
            p0 += hs[r][dbase + dd + 0] * WLy[(dbase + dd + 0) * 16 + o];
            p1 += hs[r][dbase + dd + 1] * WLy[(dbase + dd + 1) * 16 + o];
            p2 += hs[r][dbase + dd + 2] * WLy[(dbase + dd + 2) * 16 + o];
            p3 += hs[r][dbase + dd + 3] * WLy[(dbase + dd + 3) * 16 + o];
        }
        yred[q][r][o] = (p0 + p1) + (p2 + p3);
        __syncthreads();
        if (tid < 128) {
            int o2 = tid & 15, r2 = tid >> 4;
            out[((size_t)(t + 1) * BATCH + b0 + r2) * 16 + o2] =
                (yred[0][r2][o2] + yred[1][r2][o2]) +
                (yred[2][r2][o2] + yred[3][r2][o2]) + bLy[o2];
        }
    }
}

// ---------------- launch ------------------------------------------------------
extern "C" void kernel_launch(void* const* d_in, const int* in_sizes, int n_in,
                              void* d_out, int out_size)
{
    (void)in_sizes; (void)n_in; (void)out_size;
    const float* ext = (const float*)d_in[0];
    const float* obs = (const float*)d_in[1];
    const float* Wu  = (const float*)d_in[2];
    const float* bu  = (const float*)d_in[3];
    const float* Wx  = (const float*)d_in[4];
    const float* bx  = (const float*)d_in[5];
    const float* Wih = (const float*)d_in[6];
    const float* Whh = (const float*)d_in[7];
    const float* bih = (const float*)d_in[8];
    const float* bhh = (const float*)d_in[9];
    const float* W1  = (const float*)d_in[10];
    const float* b1  = (const float*)d_in[11];
    const float* W2  = (const float*)d_in[12];
    const float* b2  = (const float*)d_in[13];
    const float* WLy = (const float*)d_in[14];
    const float* bLy = (const float*)d_in[15];
    float* out = (float*)d_out;

    init_kernel<<<2048, 256>>>(out, bLy);
    embed_kernel<<<(LSEQ * BATCH) / 16, 256>>>(ext, obs, Wu, bu, Wx, bx);
    for (int t = 0; t < LSEQ; t++) {
        gru_step<<<dim3(16, 8), 256>>>(t, Wih, Whh, bih, bhh);
        ode_step<<<128, 512>>>(t, ext, W1, b1, W2, b2, WLy, bLy, out);
    }
}